// round 4
// baseline (speedup 1.0000x reference)
#include <cuda_runtime.h>
#include <cuda_bf16.h>
#include <math.h>
#include <stdint.h>

// Problem constants
#define TT 256      // T
#define BBATCH 64   // B
#define EE 512      // E (= input dim for ALL layers, since 2H = 512)
#define HH 256      // H
#define G4 1024     // 4H
#define HD2 512     // 2H
#define NTAGS 6
#define TAG_START 4
#define TAG_STOP 5
#define NEGV -1000000.0f

// ---------------- device scratch (static allocations only) ----------------
__device__ float g_x[(size_t)TT * BBATCH * EE];            // layer input / z buffer
__device__ float g_y[(size_t)TT * BBATCH * EE];            // layer output / lstm_out
__device__ float g_pre[(size_t)TT * BBATCH * 2048];        // (t,b,[dir0 1024 | dir1 1024])
__device__ float g_h[2 * 2 * HH * BBATCH];                 // [parity][dir][u][b]
__device__ float g_bias[3 * 2 * G4];                       // b_ih + b_hh combined
__device__ float g_wt[(size_t)3 * 2 * 64 * 4096];          // w_hh re-tiled: [k][ul][gate]
__device__ float g_energy[(size_t)TT * BBATCH];            // energy then softmax weights
__device__ float g_feats[(size_t)BBATCH * TT * NTAGS];     // [b][t][tag]
__device__ unsigned int g_flag[2][64];                     // per-(dir,block) step flags

// ---------------- f32x2 packed-FMA helpers ----------------
__device__ __forceinline__ void ffma2(unsigned long long& d, unsigned long long a,
                                      unsigned long long b) {
    asm("fma.rn.f32x2 %0, %1, %2, %0;" : "+l"(d) : "l"(a), "l"(b));
}
__device__ __forceinline__ unsigned long long pack2(float x, float y) {
    unsigned long long r;
    asm("mov.b64 %0, {%1, %2};" : "=l"(r) : "f"(x), "f"(y));
    return r;
}
__device__ __forceinline__ void unpack2(float& x, float& y, unsigned long long v) {
    asm("mov.b64 {%0, %1}, %2;" : "=f"(x), "=f"(y) : "l"(v));
}

// ---------------- tiny utility kernels ----------------
__global__ void zero_out_kernel(float* out) { out[0] = 0.f; }

__global__ void bias_kernel(const float* __restrict__ b_ih, const float* __restrict__ b_hh) {
    int i = blockIdx.x * blockDim.x + threadIdx.x;
    if (i < 3 * 2 * G4) g_bias[i] = b_ih[i] + b_hh[i];
}

__global__ void zero_state_kernel() {
    int i = blockIdx.x * blockDim.x + threadIdx.x;
    if (i < 2 * 2 * HH * BBATCH) g_h[i] = 0.f;
    if (i < 128) ((unsigned int*)g_flag)[i] = 0u;
}

// Re-tile w_hh (3,2,1024,256) into g_wt[(l,d,uc)][k*16 + ul*4 + g]
__global__ void wt_kernel(const float* __restrict__ whh) {
    size_t i = (size_t)blockIdx.x * blockDim.x + threadIdx.x;
    const size_t n = (size_t)3 * 2 * 64 * 4096;
    if (i >= n) return;
    int g  = i & 3;
    int ul = (i >> 2) & 3;
    int k  = (i >> 4) & 255;
    int uc = (i >> 12) & 63;
    int ld = (int)(i >> 18);
    g_wt[i] = whh[((size_t)ld * G4 + g * 256 + uc * 4 + ul) * HH + k];
}

// gather embeddings -> g_x[t][b][e]
__global__ void embed_kernel(const int* __restrict__ sent, const float* __restrict__ emb) {
    size_t i = (size_t)blockIdx.x * blockDim.x + threadIdx.x;
    const size_t n = (size_t)TT * BBATCH * EE;
    if (i >= n) return;
    int e = i & (EE - 1);
    size_t r = i >> 9;
    int b = r & (BBATCH - 1);
    int t = (int)(r >> 6);
    g_x[i] = emb[(size_t)sent[b * TT + t] * EE + e];
}

// ---------------- fp32 SGEMM via f32x2, double-buffered ----------------
// C[M,N] = A[M,K] @ W[N,K]^T + bias[N]. 128x128 tile, 256 threads, 8x8 micro-tile.
__device__ __forceinline__ void gemm_tile_compute(
    const float (*As)[128], const float (*Bs)[128],
    unsigned long long (*acc)[4], int tx, int ty)
{
#pragma unroll
    for (int kk = 0; kk < 8; kk++) {
        float ar[8], br[8];
        *(float4*)(ar)     = *(const float4*)&As[kk][ty * 8];
        *(float4*)(ar + 4) = *(const float4*)&As[kk][ty * 8 + 4];
        *(float4*)(br)     = *(const float4*)&Bs[kk][tx * 8];
        *(float4*)(br + 4) = *(const float4*)&Bs[kk][tx * 8 + 4];
        unsigned long long bp[4];
#pragma unroll
        for (int j = 0; j < 4; j++) bp[j] = pack2(br[2 * j], br[2 * j + 1]);
#pragma unroll
        for (int i = 0; i < 8; i++) {
            unsigned long long ad = pack2(ar[i], ar[i]);
#pragma unroll
            for (int j = 0; j < 4; j++) ffma2(acc[i][j], ad, bp[j]);
        }
    }
}

__global__ __launch_bounds__(256, 2) void sgemm_bias_kernel(
    const float* __restrict__ A, const float* __restrict__ W,
    const float* __restrict__ bias, float* __restrict__ C,
    int M, int N, int K)
{
    __shared__ float As[2][8][128];
    __shared__ float Bs[2][8][128];
    const int tid = threadIdx.x;
    const int bm = blockIdx.y * 128, bn = blockIdx.x * 128;
    const int lr = tid >> 1;
    const int lk = (tid & 1) * 4;
    const int tx = tid & 15, ty = tid >> 4;

    unsigned long long acc[8][4];
#pragma unroll
    for (int i = 0; i < 8; i++)
#pragma unroll
        for (int j = 0; j < 4; j++) acc[i][j] = 0ull;

    const float* Aptr = A + (size_t)(bm + lr) * K + lk;
    const float* Wptr = W + (size_t)(bn + lr) * K + lk;

    // prologue: tile 0
    {
        float4 a4 = *(const float4*)Aptr;
        float4 b4 = *(const float4*)Wptr;
        As[0][lk + 0][lr] = a4.x; As[0][lk + 1][lr] = a4.y;
        As[0][lk + 2][lr] = a4.z; As[0][lk + 3][lr] = a4.w;
        Bs[0][lk + 0][lr] = b4.x; Bs[0][lk + 1][lr] = b4.y;
        Bs[0][lk + 2][lr] = b4.z; Bs[0][lk + 3][lr] = b4.w;
    }
    __syncthreads();

    const int nt = K >> 3;
    for (int t = 1; t < nt; t++) {
        float4 na = *(const float4*)(Aptr + t * 8);
        float4 nb = *(const float4*)(Wptr + t * 8);
        const int cb = (t - 1) & 1, pb = t & 1;
        gemm_tile_compute(As[cb], Bs[cb], acc, tx, ty);
        As[pb][lk + 0][lr] = na.x; As[pb][lk + 1][lr] = na.y;
        As[pb][lk + 2][lr] = na.z; As[pb][lk + 3][lr] = na.w;
        Bs[pb][lk + 0][lr] = nb.x; Bs[pb][lk + 1][lr] = nb.y;
        Bs[pb][lk + 2][lr] = nb.z; Bs[pb][lk + 3][lr] = nb.w;
        __syncthreads();
    }
    gemm_tile_compute(As[(nt - 1) & 1], Bs[(nt - 1) & 1], acc, tx, ty);

    float bb[8];
#pragma unroll
    for (int j = 0; j < 8; j++) bb[j] = bias[bn + tx * 8 + j];
#pragma unroll
    for (int i = 0; i < 8; i++) {
        float cv[8];
#pragma unroll
        for (int j = 0; j < 4; j++) unpack2(cv[2 * j], cv[2 * j + 1], acc[i][j]);
        size_t row = (size_t)(bm + ty * 8 + i);
        float4 o0, o1;
        o0.x = cv[0] + bb[0]; o0.y = cv[1] + bb[1];
        o0.z = cv[2] + bb[2]; o0.w = cv[3] + bb[3];
        o1.x = cv[4] + bb[4]; o1.y = cv[5] + bb[5];
        o1.z = cv[6] + bb[6]; o1.w = cv[7] + bb[7];
        *(float4*)(C + row * N + bn + tx * 8)     = o0;
        *(float4*)(C + row * N + bn + tx * 8 + 4) = o1;
    }
}

// ---------------- persistent LSTM layer kernel ----------------
// grid=128 (d = bi>>6, uchunk = bi&63), block=128, all co-resident.
// Per-step sync: per-block release flags + parallel acquire polling (no atomics).
__global__ __launch_bounds__(128) void lstm_layer_kernel(
    const float* __restrict__ wt_l,   // g_wt + l*2*64*4096
    const float* __restrict__ pre,    // g_pre
    float* __restrict__ out)
{
    extern __shared__ float sm[];
    float* hs = sm;             // 16384 floats
    float* ws = sm + 16384;     // 4096 floats
    const int d  = blockIdx.x >> 6;
    const int uc = blockIdx.x & 63;
    const int u0 = uc * 4;
    const int tid = threadIdx.x;
    const int ul = tid & 3;
    const int b0 = (tid >> 2) * 2;
    const int u  = u0 + ul;

    // load W_hh tile once for the whole layer
    const float4* wsrc4 = (const float4*)(wt_l + ((size_t)d * 64 + uc) * 4096);
    float4* ws4 = (float4*)ws;
    for (int i = tid; i < 1024; i += 128) ws4[i] = wsrc4[i];

    float c0 = 0.f, c1 = 0.f;                 // c-state in registers
    float4* hs4 = (float4*)hs;
    const unsigned int* myflags = &g_flag[d][0];

    for (int s = 0; s < TT; s++) {
        const int tt = d ? (TT - 1 - s) : s;
        const int rp = s & 1, wp = rp ^ 1;

        // prefetch pre-activation (independent of the barrier)
        const float* prow = pre + (size_t)tt * BBATCH * 2048 + (size_t)d * G4;
        float p0[4], p1[4];
#pragma unroll
        for (int g = 0; g < 4; g++) {
            p0[g] = __ldg(&prow[(size_t)b0 * 2048 + g * 256 + u]);
            p1[g] = __ldg(&prow[(size_t)(b0 + 1) * 2048 + g * 256 + u]);
        }

        // wait: all 64 blocks of this direction finished step s-1
        if (s) {
            if (tid < 64) {
                const unsigned int* fp = myflags + tid;
                unsigned int v;
                do {
                    asm volatile("ld.acquire.gpu.global.u32 %0, [%1];"
                                 : "=r"(v) : "l"(fp) : "memory");
                } while (v < (unsigned int)s);
            }
            __syncthreads();
        }

        // stage h (parity rp) for this direction into smem, via L2
        const float4* hsrc4 = (const float4*)(g_h + (size_t)(rp * 2 + d) * (HH * BBATCH));
#pragma unroll
        for (int i = tid; i < 4096; i += 128) hs4[i] = __ldcg(hsrc4 + i);
        __syncthreads();

        unsigned long long aA01 = 0ull, aA23 = 0ull, aB01 = 0ull, aB23 = 0ull;
#pragma unroll 8
        for (int k = 0; k < 256; k++) {
            float2 hv = *(const float2*)&hs[k * 64 + b0];
            float4 wv = *(const float4*)&ws[k * 16 + ul * 4];
            unsigned long long w01 = pack2(wv.x, wv.y);
            unsigned long long w23 = pack2(wv.z, wv.w);
            unsigned long long hx = pack2(hv.x, hv.x);
            unsigned long long hy = pack2(hv.y, hv.y);
            ffma2(aA01, hx, w01); ffma2(aA23, hx, w23);
            ffma2(aB01, hy, w01); ffma2(aB23, hy, w23);
        }
        float a00, a01, a02, a03, a10, a11, a12, a13;
        unpack2(a00, a01, aA01); unpack2(a02, a03, aA23);
        unpack2(a10, a11, aB01); unpack2(a12, a13, aB23);

#pragma unroll
        for (int bb = 0; bb < 2; bb++) {
            int b = b0 + bb;
            float gi = (bb ? p1[0] : p0[0]) + (bb ? a10 : a00);
            float gf = (bb ? p1[1] : p0[1]) + (bb ? a11 : a01);
            float gg = (bb ? p1[2] : p0[2]) + (bb ? a12 : a02);
            float go = (bb ? p1[3] : p0[3]) + (bb ? a13 : a03);
            float iv = 1.f / (1.f + expf(-gi));
            float fv = 1.f / (1.f + expf(-gf));
            float gv = tanhf(gg);
            float ov = 1.f / (1.f + expf(-go));
            float cprev = bb ? c1 : c0;
            float c = fv * cprev + iv * gv;
            if (bb) c1 = c; else c0 = c;
            float h = ov * tanhf(c);
            g_h[(size_t)(wp * 2 + d) * (HH * BBATCH) + u * 64 + b] = h;
            out[(size_t)tt * BBATCH * HD2 + (size_t)b * HD2 + d * HH + u] = h;
        }

        // release: signal this block finished step s (value s+1)
        __syncthreads();
        if (tid == 0) {
            asm volatile("st.release.gpu.global.u32 [%0], %1;"
                         :: "l"(&g_flag[d][uc]), "r"((unsigned int)(s + 1)) : "memory");
        }
    }
}

// ---------------- attention ----------------
__global__ __launch_bounds__(256) void energy_kernel(const float* __restrict__ z,
                                                     const float* __restrict__ aw2,
                                                     const float* __restrict__ ab2)
{
    int w = threadIdx.x >> 5, lane = threadIdx.x & 31;
    int r = blockIdx.x * 8 + w;
    const float* zr = z + (size_t)r * 512;
    float acc = 0.f;
#pragma unroll
    for (int j = 0; j < 16; j++) {
        int k = lane + j * 32;
        acc += tanhf(zr[k]) * aw2[k];
    }
#pragma unroll
    for (int o = 16; o > 0; o >>= 1) acc += __shfl_down_sync(0xffffffffu, acc, o);
    if (lane == 0) g_energy[r] = acc + ab2[0];
}

__global__ __launch_bounds__(256) void softmax_kernel() {
    __shared__ float red[256];
    int b = blockIdx.x, t = threadIdx.x;
    float e = g_energy[t * 64 + b];
    red[t] = e;
    __syncthreads();
    for (int s = 128; s > 0; s >>= 1) {
        if (t < s) red[t] = fmaxf(red[t], red[t + s]);
        __syncthreads();
    }
    float m = red[0];
    __syncthreads();
    float p = expf(e - m);
    red[t] = p;
    __syncthreads();
    for (int s = 128; s > 0; s >>= 1) {
        if (t < s) red[t] += red[t + s];
        __syncthreads();
    }
    g_energy[t * 64 + b] = p / red[0];
}

__global__ __launch_bounds__(256) void feats_kernel(const float* __restrict__ y,
                                                    const float* __restrict__ hw,
                                                    const float* __restrict__ hb)
{
    int w = threadIdx.x >> 5, lane = threadIdx.x & 31;
    int r = blockIdx.x * 8 + w;
    const float* yr = y + (size_t)r * 512;
    float acc[NTAGS];
#pragma unroll
    for (int i = 0; i < NTAGS; i++) acc[i] = 0.f;
#pragma unroll
    for (int j = 0; j < 16; j++) {
        int k = lane + j * 32;
        float v = yr[k];
#pragma unroll
        for (int i = 0; i < NTAGS; i++) acc[i] += v * hw[i * 512 + k];
    }
#pragma unroll
    for (int i = 0; i < NTAGS; i++)
#pragma unroll
        for (int o = 16; o > 0; o >>= 1) acc[i] += __shfl_down_sync(0xffffffffu, acc[i], o);
    if (lane == 0) {
        float wt = 1.f + g_energy[r];
        int b = r & 63, t = r >> 6;
#pragma unroll
        for (int i = 0; i < NTAGS; i++)
            g_feats[((size_t)b * TT + t) * NTAGS + i] = wt * acc[i] + hb[i];
    }
}

// ---------------- CRF ----------------
__global__ __launch_bounds__(32) void crf_kernel(const int* __restrict__ tags,
                                                 const float* __restrict__ mask,
                                                 const float* __restrict__ trans,
                                                 float* __restrict__ out)
{
    __shared__ float tr[36];
    int b = blockIdx.x, lid = threadIdx.x;
    for (int i = lid; i < 36; i += 32) tr[i] = trans[i];
    __syncwarp();

    const int ii = lid % NTAGS;
    const float* fb = g_feats + (size_t)b * TT * NTAGS;
    const float* mb = mask + (size_t)b * TT;

    float fv = (ii == TAG_START) ? 0.f : NEGV;
    for (int t = 0; t < TT; t++) {
        float fj[NTAGS];
#pragma unroll
        for (int j = 0; j < NTAGS; j++) fj[j] = __shfl_sync(0xffffffffu, fv, j);
        float v[NTAGS];
        float m = -3.4e38f;
#pragma unroll
        for (int j = 0; j < NTAGS; j++) {
            v[j] = fj[j] + tr[ii * NTAGS + j];
            m = fmaxf(m, v[j]);
        }
        float ssum = 0.f;
#pragma unroll
        for (int j = 0; j < NTAGS; j++) ssum += expf(v[j] - m);
        float nxt = m + logf(ssum) + fb[t * NTAGS + ii];
        fv = (mb[t] > 0.f) ? nxt : fv;
    }
    float sv = fv + tr[TAG_STOP * NTAGS + ii];
    float gvals[NTAGS];
#pragma unroll
    for (int j = 0; j < NTAGS; j++) gvals[j] = __shfl_sync(0xffffffffu, sv, j);
    float m2 = -3.4e38f;
#pragma unroll
    for (int j = 0; j < NTAGS; j++) m2 = fmaxf(m2, gvals[j]);
    float s2 = 0.f;
#pragma unroll
    for (int j = 0; j < NTAGS; j++) s2 += expf(gvals[j] - m2);
    float fwd = m2 + logf(s2);

    float gold = 0.f, msum = 0.f;
    for (int t = lid; t < TT; t += 32) {
        int cur = tags[b * TT + t];
        int prev = t ? tags[b * TT + t - 1] : TAG_START;
        float mm = mb[t];
        gold += (fb[t * NTAGS + cur] + tr[cur * NTAGS + prev]) * mm;
        msum += mm;
    }
#pragma unroll
    for (int o = 16; o > 0; o >>= 1) {
        gold += __shfl_down_sync(0xffffffffu, gold, o);
        msum += __shfl_down_sync(0xffffffffu, msum, o);
    }
    if (lid == 0) {
        int sl = (int)(msum + 0.5f);
        int last = (sl > 0) ? tags[b * TT + sl - 1] : TAG_START;
        gold += tr[TAG_STOP * NTAGS + last];
        atomicAdd(out, (fwd - gold) * (1.f / 64.f));
    }
}

// ---------------- launch ----------------
extern "C" void kernel_launch(void* const* d_in, const int* in_sizes, int n_in,
                              void* d_out, int out_size)
{
    const int*   sentences = (const int*)d_in[0];
    const int*   tags      = (const int*)d_in[1];
    const float* mask      = (const float*)d_in[2];
    const float* embed     = (const float*)d_in[3];
    const float* w_ih      = (const float*)d_in[4];
    const float* w_hh      = (const float*)d_in[5];
    const float* b_ih      = (const float*)d_in[6];
    const float* b_hh      = (const float*)d_in[7];
    const float* aw1       = (const float*)d_in[8];
    const float* ab1       = (const float*)d_in[9];
    const float* aw2       = (const float*)d_in[10];
    const float* ab2       = (const float*)d_in[11];
    const float* hw        = (const float*)d_in[12];
    const float* hb        = (const float*)d_in[13];
    const float* trans     = (const float*)d_in[14];
    float* out = (float*)d_out;

    const int STEP_SMEM = (16384 + 4096) * 4;  // 80 KB
    cudaFuncSetAttribute(lstm_layer_kernel, cudaFuncAttributeMaxDynamicSharedMemorySize, STEP_SMEM);

    zero_out_kernel<<<1, 1>>>(out);
    bias_kernel<<<24, 256>>>(b_ih, b_hh);
    wt_kernel<<<6144, 256>>>(w_hh);
    embed_kernel<<<32768, 256>>>(sentences, embed);

    float *px, *py, *ppre, *pbias, *pwt;
    cudaGetSymbolAddress((void**)&px, g_x);
    cudaGetSymbolAddress((void**)&py, g_y);
    cudaGetSymbolAddress((void**)&ppre, g_pre);
    cudaGetSymbolAddress((void**)&pbias, g_bias);
    cudaGetSymbolAddress((void**)&pwt, g_wt);

    const int M = TT * BBATCH;  // 16384
    float* lin = px;
    float* lout = py;
    for (int l = 0; l < 3; l++) {
        zero_state_kernel<<<128, 256>>>();
        dim3 g1(2048 / 128, M / 128);
        sgemm_bias_kernel<<<g1, 256>>>(lin, w_ih + (size_t)l * 2 * G4 * EE,
                                       pbias + l * 2048, ppre, M, 2048, EE);
        const float* wtl = pwt + (size_t)l * 2 * 64 * 4096;
        lstm_layer_kernel<<<128, 128, STEP_SMEM>>>(wtl, ppre, lout);
        float* tmp = lin; lin = lout; lout = tmp;
    }
    float* lstm_out = lin;   // == py
    float* zbuf = lout;      // == px

    dim3 g2(512 / 128, M / 128);
    sgemm_bias_kernel<<<g2, 256>>>(lstm_out, aw1, ab1, zbuf, M, 512, EE);
    energy_kernel<<<M / 8, 256>>>(zbuf, aw2, ab2);
    softmax_kernel<<<BBATCH, 256>>>();
    feats_kernel<<<M / 8, 256>>>(lstm_out, hw, hb);
    crf_kernel<<<BBATCH, 32>>>(tags, mask, trans, out);
}

// round 5
// speedup vs baseline: 1.4534x; 1.4534x over previous
#include <cuda_runtime.h>
#include <cuda_bf16.h>
#include <math.h>
#include <stdint.h>

// Problem constants
#define TT 256      // T
#define BBATCH 64   // B
#define EE 512      // E (= input dim for ALL layers, since 2H = 512)
#define HH 256      // H
#define G4 1024     // 4H
#define HD2 512     // 2H
#define NTAGS 6
#define TAG_START 4
#define TAG_STOP 5
#define NEGV -1000000.0f

// ---------------- device scratch (static allocations only) ----------------
__device__ float g_x[(size_t)TT * BBATCH * EE];            // layer input / z buffer
__device__ float g_y[(size_t)TT * BBATCH * EE];            // layer output / lstm_out
__device__ float g_pre[(size_t)TT * BBATCH * 2048];        // (t,b,[dir0 1024 | dir1 1024])
__device__ float g_hb[2 * 2 * 8 * 2048];                   // [parity][dir][bg][u*8+b] h-state
__device__ float g_bias[3 * 2 * G4];                       // b_ih + b_hh combined
__device__ float g_wt[(size_t)3 * 2 * 8 * 32768];          // w_hh re-tiled per (l,d,ugi): [k][up][g][usel]
__device__ float g_energy[(size_t)TT * BBATCH];            // energy then softmax weights
__device__ float g_feats[(size_t)BBATCH * TT * NTAGS];     // [b][t][tag]
__device__ unsigned int g_flag2[128];                      // [d*64 + bg*8 + ugi] step flags

// ---------------- f32x2 packed-FMA helpers ----------------
__device__ __forceinline__ void ffma2(unsigned long long& d, unsigned long long a,
                                      unsigned long long b) {
    asm("fma.rn.f32x2 %0, %1, %2, %0;" : "+l"(d) : "l"(a), "l"(b));
}
__device__ __forceinline__ unsigned long long pack2(float x, float y) {
    unsigned long long r;
    asm("mov.b64 %0, {%1, %2};" : "=l"(r) : "f"(x), "f"(y));
    return r;
}
__device__ __forceinline__ void unpack2(float& x, float& y, unsigned long long v) {
    asm("mov.b64 {%0, %1}, %2;" : "=f"(x), "=f"(y) : "l"(v));
}

// ---------------- tiny utility kernels ----------------
__global__ void zero_out_kernel(float* out) { out[0] = 0.f; }

__global__ void bias_kernel(const float* __restrict__ b_ih, const float* __restrict__ b_hh) {
    int i = blockIdx.x * blockDim.x + threadIdx.x;
    if (i < 3 * 2 * G4) g_bias[i] = b_ih[i] + b_hh[i];
}

// zero h parity buffers + step flags (per layer)
__global__ void zero_state_kernel() {
    int i = blockIdx.x * blockDim.x + threadIdx.x;
    if (i < 2 * 2 * 8 * 2048) g_hb[i] = 0.f;
    if (i < 128) g_flag2[i] = 0u;
}

// Re-tile w_hh (3,2,1024,256) into g_wt[(l,d,ugi)][k][up][g][usel]
// u = ugi*32 + up*2 + usel; gate g in {i,f,g,o}
__global__ void wt_kernel(const float* __restrict__ whh) {
    size_t i = (size_t)blockIdx.x * blockDim.x + threadIdx.x;
    const size_t n = (size_t)3 * 2 * 8 * 32768;
    if (i >= n) return;
    int usel = i & 1;
    int g    = (i >> 1) & 3;
    int up   = (i >> 3) & 15;
    int k    = (i >> 7) & 255;
    int ugi  = (i >> 15) & 7;
    int ld   = (int)(i >> 18);   // l*2 + d, 0..5
    int u = ugi * 32 + up * 2 + usel;
    g_wt[i] = whh[((size_t)ld * G4 + g * 256 + u) * HH + k];
}

// gather embeddings -> g_x[t][b][e]
__global__ void embed_kernel(const int* __restrict__ sent, const float* __restrict__ emb) {
    size_t i = (size_t)blockIdx.x * blockDim.x + threadIdx.x;
    const size_t n = (size_t)TT * BBATCH * EE;
    if (i >= n) return;
    int e = i & (EE - 1);
    size_t r = i >> 9;
    int b = r & (BBATCH - 1);
    int t = (int)(r >> 6);
    g_x[i] = emb[(size_t)sent[b * TT + t] * EE + e];
}

// ---------------- fp32 SGEMM: C[M,N] = A[M,K] @ W[N,K]^T + bias[N] ----------------
// (R1-proven version) 128x128 tile, 256 threads, 8x8 micro-tile, K-tile 8.
__global__ __launch_bounds__(256) void sgemm_bias_kernel(
    const float* __restrict__ A, const float* __restrict__ W,
    const float* __restrict__ bias, float* __restrict__ C,
    int M, int N, int K)
{
    __shared__ float As[8][128];
    __shared__ float Bs[8][128];
    const int tid = threadIdx.x;
    const int bm = blockIdx.y * 128, bn = blockIdx.x * 128;
    const int lr = tid >> 1;
    const int lk = (tid & 1) * 4;
    const int tx = tid & 15, ty = tid >> 4;

    float acc[8][8];
#pragma unroll
    for (int i = 0; i < 8; i++)
#pragma unroll
        for (int j = 0; j < 8; j++) acc[i][j] = 0.f;

    const float* Aptr = A + (size_t)(bm + lr) * K + lk;
    const float* Wptr = W + (size_t)(bn + lr) * K + lk;

    for (int k0 = 0; k0 < K; k0 += 8) {
        float4 a4 = *(const float4*)(Aptr + k0);
        float4 b4 = *(const float4*)(Wptr + k0);
        As[lk + 0][lr] = a4.x; As[lk + 1][lr] = a4.y; As[lk + 2][lr] = a4.z; As[lk + 3][lr] = a4.w;
        Bs[lk + 0][lr] = b4.x; Bs[lk + 1][lr] = b4.y; Bs[lk + 2][lr] = b4.z; Bs[lk + 3][lr] = b4.w;
        __syncthreads();
#pragma unroll
        for (int kk = 0; kk < 8; kk++) {
            float ar[8], br[8];
            *(float4*)(ar)     = *(const float4*)&As[kk][ty * 8];
            *(float4*)(ar + 4) = *(const float4*)&As[kk][ty * 8 + 4];
            *(float4*)(br)     = *(const float4*)&Bs[kk][tx * 8];
            *(float4*)(br + 4) = *(const float4*)&Bs[kk][tx * 8 + 4];
#pragma unroll
            for (int i = 0; i < 8; i++)
#pragma unroll
                for (int j = 0; j < 8; j++) acc[i][j] += ar[i] * br[j];
        }
        __syncthreads();
    }
    float bb[8];
#pragma unroll
    for (int j = 0; j < 8; j++) bb[j] = bias[bn + tx * 8 + j];
#pragma unroll
    for (int i = 0; i < 8; i++) {
        size_t row = (size_t)(bm + ty * 8 + i);
        float4 o0, o1;
        o0.x = acc[i][0] + bb[0]; o0.y = acc[i][1] + bb[1];
        o0.z = acc[i][2] + bb[2]; o0.w = acc[i][3] + bb[3];
        o1.x = acc[i][4] + bb[4]; o1.y = acc[i][5] + bb[5];
        o1.z = acc[i][6] + bb[6]; o1.w = acc[i][7] + bb[7];
        *(float4*)(C + row * N + bn + tx * 8)     = o0;
        *(float4*)(C + row * N + bn + tx * 8 + 4) = o1;
    }
}

// ---------------- persistent LSTM layer kernel, batch-group partitioned ----------------
// grid = 128: d = bi>>6, bg = (bi>>3)&7 (8 batches), ugi = bi&7 (32 hidden units).
// Sync group = 8 blocks sharing (d,bg). block = 128 threads: b = tid&7, up = tid>>3.
// Each thread owns cells (u0=ugi*32+up*2, b) and (u0+1, b); c-state in registers.
// W_hh slice (128KB) in smem for the whole layer; h exchange = 8KB/group/step via L2.
__global__ __launch_bounds__(128) void lstm_layer_kernel(
    const float* __restrict__ wt_l,   // g_wt + l*2*8*32768
    const float* __restrict__ pre,    // g_pre
    float* __restrict__ out)
{
    extern __shared__ float sm[];
    float* ws = sm;              // 32768 floats (128KB)
    float* hs = sm + 32768;      // 2048 floats (8KB)
    const int bi  = blockIdx.x;
    const int d   = bi >> 6;
    const int bg  = (bi >> 3) & 7;
    const int ugi = bi & 7;
    const int tid = threadIdx.x;
    const int b   = tid & 7;
    const int up  = tid >> 3;          // 0..15
    const int u0  = ugi * 32 + up * 2;
    const int bglob = bg * 8 + b;

    // load W_hh slice once for the whole layer (8192 float4)
    const float4* wsrc = (const float4*)(wt_l + ((size_t)(d * 8 + ugi)) * 32768);
    float4* ws4 = (float4*)ws;
    for (int i = tid; i < 8192; i += 128) ws4[i] = wsrc[i];

    unsigned int* flags = &g_flag2[d * 64 + bg * 8];
    float4* hs4 = (float4*)hs;
    float c0 = 0.f, c1 = 0.f;

    for (int s = 0; s < TT; s++) {
        const int tt = d ? (TT - 1 - s) : s;
        const int rp = s & 1, wp = rp ^ 1;

        // prefetch pre-activations (independent of the barrier)
        const float* prow = pre + ((size_t)tt * BBATCH + bglob) * 2048 + d * G4;
        float p[8];
#pragma unroll
        for (int g = 0; g < 4; g++) {
            float2 pv = *(const float2*)&prow[g * 256 + u0];
            p[2 * g] = pv.x; p[2 * g + 1] = pv.y;
        }

        // wait: all 8 blocks of this group finished step s-1
        if (s) {
            if (tid < 8) {
                const unsigned int* fp = flags + tid;
                unsigned int v;
                do {
                    asm volatile("ld.acquire.gpu.global.u32 %0, [%1];"
                                 : "=r"(v) : "l"(fp) : "memory");
                } while (v < (unsigned int)s);
            }
            __syncthreads();
        }

        // stage this group's h (parity rp) into smem via L2: 512 float4
        const float4* hsrc = (const float4*)(g_hb + (((size_t)rp * 2 + d) * 8 + bg) * 2048);
#pragma unroll
        for (int i = tid; i < 512; i += 128) hs4[i] = __ldcg(hsrc + i);
        __syncthreads();

        // recurrence dot products: 4 gate-pairs (u0,u1) via f32x2
        unsigned long long a0 = 0ull, a1 = 0ull, a2 = 0ull, a3 = 0ull;
        const float* wbase = ws + up * 8;
#pragma unroll 8
        for (int k = 0; k < 256; k++) {
            float hv = hs[k * 8 + b];
            unsigned long long hh = pack2(hv, hv);
            const float* wk = wbase + k * 128;
            ulonglong2 w01 = *(const ulonglong2*)(wk);       // (i_u0,i_u1),(f_u0,f_u1)
            ulonglong2 w23 = *(const ulonglong2*)(wk + 4);   // (g_u0,g_u1),(o_u0,o_u1)
            ffma2(a0, hh, w01.x); ffma2(a1, hh, w01.y);
            ffma2(a2, hh, w23.x); ffma2(a3, hh, w23.y);
        }
        float i0, i1, f0, f1, gg0, gg1, o0, o1;
        unpack2(i0, i1, a0); unpack2(f0, f1, a1);
        unpack2(gg0, gg1, a2); unpack2(o0, o1, a3);

        // cell updates (u0 and u0+1)
        float gi0 = p[0] + i0, gf0 = p[2] + f0, gg0v = p[4] + gg0, go0 = p[6] + o0;
        float gi1 = p[1] + i1, gf1 = p[3] + f1, gg1v = p[5] + gg1, go1 = p[7] + o1;
        float iv0 = 1.f / (1.f + expf(-gi0));
        float fv0 = 1.f / (1.f + expf(-gf0));
        float gv0 = tanhf(gg0v);
        float ov0 = 1.f / (1.f + expf(-go0));
        c0 = fv0 * c0 + iv0 * gv0;
        float h0 = ov0 * tanhf(c0);
        float iv1 = 1.f / (1.f + expf(-gi1));
        float fv1 = 1.f / (1.f + expf(-gf1));
        float gv1 = tanhf(gg1v);
        float ov1 = 1.f / (1.f + expf(-go1));
        c1 = fv1 * c1 + iv1 * gv1;
        float h1 = ov1 * tanhf(c1);

        // store h for next step (parity wp) and to layer output
        float* hdst = g_hb + (((size_t)wp * 2 + d) * 8 + bg) * 2048;
        hdst[u0 * 8 + b]       = h0;
        hdst[(u0 + 1) * 8 + b] = h1;
        float2 ho; ho.x = h0; ho.y = h1;
        *(float2*)(out + ((size_t)tt * BBATCH + bglob) * HD2 + d * HH + u0) = ho;

        // release: signal this block finished step s
        __syncthreads();
        if (tid == 0) {
            asm volatile("st.release.gpu.global.u32 [%0], %1;"
                         :: "l"(flags + ugi), "r"((unsigned int)(s + 1)) : "memory");
        }
    }
}

// ---------------- attention ----------------
__global__ __launch_bounds__(256) void energy_kernel(const float* __restrict__ z,
                                                     const float* __restrict__ aw2,
                                                     const float* __restrict__ ab2)
{
    int w = threadIdx.x >> 5, lane = threadIdx.x & 31;
    int r = blockIdx.x * 8 + w;
    const float* zr = z + (size_t)r * 512;
    float acc = 0.f;
#pragma unroll
    for (int j = 0; j < 16; j++) {
        int k = lane + j * 32;
        acc += tanhf(zr[k]) * aw2[k];
    }
#pragma unroll
    for (int o = 16; o > 0; o >>= 1) acc += __shfl_down_sync(0xffffffffu, acc, o);
    if (lane == 0) g_energy[r] = acc + ab2[0];
}

__global__ __launch_bounds__(256) void softmax_kernel() {
    __shared__ float red[256];
    int b = blockIdx.x, t = threadIdx.x;
    float e = g_energy[t * 64 + b];
    red[t] = e;
    __syncthreads();
    for (int s = 128; s > 0; s >>= 1) {
        if (t < s) red[t] = fmaxf(red[t], red[t + s]);
        __syncthreads();
    }
    float m = red[0];
    __syncthreads();
    float p = expf(e - m);
    red[t] = p;
    __syncthreads();
    for (int s = 128; s > 0; s >>= 1) {
        if (t < s) red[t] += red[t + s];
        __syncthreads();
    }
    g_energy[t * 64 + b] = p / red[0];
}

__global__ __launch_bounds__(256) void feats_kernel(const float* __restrict__ y,
                                                    const float* __restrict__ hw,
                                                    const float* __restrict__ hb)
{
    int w = threadIdx.x >> 5, lane = threadIdx.x & 31;
    int r = blockIdx.x * 8 + w;
    const float* yr = y + (size_t)r * 512;
    float acc[NTAGS];
#pragma unroll
    for (int i = 0; i < NTAGS; i++) acc[i] = 0.f;
#pragma unroll
    for (int j = 0; j < 16; j++) {
        int k = lane + j * 32;
        float v = yr[k];
#pragma unroll
        for (int i = 0; i < NTAGS; i++) acc[i] += v * hw[i * 512 + k];
    }
#pragma unroll
    for (int i = 0; i < NTAGS; i++)
#pragma unroll
        for (int o = 16; o > 0; o >>= 1) acc[i] += __shfl_down_sync(0xffffffffu, acc[i], o);
    if (lane == 0) {
        float wt = 1.f + g_energy[r];
        int b = r & 63, t = r >> 6;
#pragma unroll
        for (int i = 0; i < NTAGS; i++)
            g_feats[((size_t)b * TT + t) * NTAGS + i] = wt * acc[i] + hb[i];
    }
}

// ---------------- CRF ----------------
__global__ __launch_bounds__(32) void crf_kernel(const int* __restrict__ tags,
                                                 const float* __restrict__ mask,
                                                 const float* __restrict__ trans,
                                                 float* __restrict__ out)
{
    __shared__ float tr[36];
    int b = blockIdx.x, lid = threadIdx.x;
    for (int i = lid; i < 36; i += 32) tr[i] = trans[i];
    __syncwarp();

    const int ii = lid % NTAGS;
    const float* fb = g_feats + (size_t)b * TT * NTAGS;
    const float* mb = mask + (size_t)b * TT;

    float fv = (ii == TAG_START) ? 0.f : NEGV;
    for (int t = 0; t < TT; t++) {
        float fj[NTAGS];
#pragma unroll
        for (int j = 0; j < NTAGS; j++) fj[j] = __shfl_sync(0xffffffffu, fv, j);
        float v[NTAGS];
        float m = -3.4e38f;
#pragma unroll
        for (int j = 0; j < NTAGS; j++) {
            v[j] = fj[j] + tr[ii * NTAGS + j];
            m = fmaxf(m, v[j]);
        }
        float ssum = 0.f;
#pragma unroll
        for (int j = 0; j < NTAGS; j++) ssum += expf(v[j] - m);
        float nxt = m + logf(ssum) + fb[t * NTAGS + ii];
        fv = (mb[t] > 0.f) ? nxt : fv;
    }
    float sv = fv + tr[TAG_STOP * NTAGS + ii];
    float gvals[NTAGS];
#pragma unroll
    for (int j = 0; j < NTAGS; j++) gvals[j] = __shfl_sync(0xffffffffu, sv, j);
    float m2 = -3.4e38f;
#pragma unroll
    for (int j = 0; j < NTAGS; j++) m2 = fmaxf(m2, gvals[j]);
    float s2 = 0.f;
#pragma unroll
    for (int j = 0; j < NTAGS; j++) s2 += expf(gvals[j] - m2);
    float fwd = m2 + logf(s2);

    float gold = 0.f, msum = 0.f;
    for (int t = lid; t < TT; t += 32) {
        int cur = tags[b * TT + t];
        int prev = t ? tags[b * TT + t - 1] : TAG_START;
        float mm = mb[t];
        gold += (fb[t * NTAGS + cur] + tr[cur * NTAGS + prev]) * mm;
        msum += mm;
    }
#pragma unroll
    for (int o = 16; o > 0; o >>= 1) {
        gold += __shfl_down_sync(0xffffffffu, gold, o);
        msum += __shfl_down_sync(0xffffffffu, msum, o);
    }
    if (lid == 0) {
        int sl = (int)(msum + 0.5f);
        int last = (sl > 0) ? tags[b * TT + sl - 1] : TAG_START;
        gold += tr[TAG_STOP * NTAGS + last];
        atomicAdd(out, (fwd - gold) * (1.f / 64.f));
    }
}

// ---------------- launch ----------------
extern "C" void kernel_launch(void* const* d_in, const int* in_sizes, int n_in,
                              void* d_out, int out_size)
{
    const int*   sentences = (const int*)d_in[0];
    const int*   tags      = (const int*)d_in[1];
    const float* mask      = (const float*)d_in[2];
    const float* embed     = (const float*)d_in[3];
    const float* w_ih      = (const float*)d_in[4];
    const float* w_hh      = (const float*)d_in[5];
    const float* b_ih      = (const float*)d_in[6];
    const float* b_hh      = (const float*)d_in[7];
    const float* aw1       = (const float*)d_in[8];
    const float* ab1       = (const float*)d_in[9];
    const float* aw2       = (const float*)d_in[10];
    const float* ab2       = (const float*)d_in[11];
    const float* hw        = (const float*)d_in[12];
    const float* hb        = (const float*)d_in[13];
    const float* trans     = (const float*)d_in[14];
    float* out = (float*)d_out;

    const int STEP_SMEM = (32768 + 2048) * 4;  // 136 KB
    cudaFuncSetAttribute(lstm_layer_kernel, cudaFuncAttributeMaxDynamicSharedMemorySize, STEP_SMEM);

    zero_out_kernel<<<1, 1>>>(out);
    bias_kernel<<<24, 256>>>(b_ih, b_hh);
    wt_kernel<<<6144, 256>>>(w_hh);
    embed_kernel<<<32768, 256>>>(sentences, embed);

    float *px, *py, *ppre, *pbias, *pwt;
    cudaGetSymbolAddress((void**)&px, g_x);
    cudaGetSymbolAddress((void**)&py, g_y);
    cudaGetSymbolAddress((void**)&ppre, g_pre);
    cudaGetSymbolAddress((void**)&pbias, g_bias);
    cudaGetSymbolAddress((void**)&pwt, g_wt);

    const int M = TT * BBATCH;  // 16384
    float* lin = px;
    float* lout = py;
    for (int l = 0; l < 3; l++) {
        zero_state_kernel<<<256, 256>>>();
        dim3 g1(2048 / 128, M / 128);
        sgemm_bias_kernel<<<g1, 256>>>(lin, w_ih + (size_t)l * 2 * G4 * EE,
                                       pbias + l * 2048, ppre, M, 2048, EE);
        const float* wtl = pwt + (size_t)l * 2 * 8 * 32768;
        lstm_layer_kernel<<<128, 128, STEP_SMEM>>>(wtl, ppre, lout);
        float* tmp = lin; lin = lout; lout = tmp;
    }
    float* lstm_out = lin;   // == py
    float* zbuf = lout;      // == px

    dim3 g2(512 / 128, M / 128);
    sgemm_bias_kernel<<<g2, 256>>>(lstm_out, aw1, ab1, zbuf, M, 512, EE);
    energy_kernel<<<M / 8, 256>>>(zbuf, aw2, ab2);
    softmax_kernel<<<BBATCH, 256>>>();
    feats_kernel<<<M / 8, 256>>>(lstm_out, hw, hb);
    crf_kernel<<<BBATCH, 32>>>(tags, mask, trans, out);
}

// round 6
// speedup vs baseline: 1.8684x; 1.2855x over previous
#include <cuda_runtime.h>
#include <cuda_bf16.h>
#include <math.h>
#include <stdint.h>

// Problem constants
#define TT 256      // T
#define BBATCH 64   // B
#define EE 512      // E (= input dim for ALL layers, since 2H = 512)
#define HH 256      // H
#define G4 1024     // 4H
#define HD2 512     // 2H
#define NTAGS 6
#define TAG_START 4
#define TAG_STOP 5
#define NEGV -1000000.0f

// ---------------- device scratch (static allocations only) ----------------
__device__ float g_x[(size_t)TT * BBATCH * EE];            // layer input / z buffer
__device__ float g_y[(size_t)TT * BBATCH * EE];            // layer output / lstm_out
__device__ float g_pre[(size_t)TT * BBATCH * 2048];        // (t,b,[dir0 1024 | dir1 1024])
__device__ float g_hb[2 * 2 * 8 * 2048];                   // [parity][dir][bg][u*8+b] h-state
__device__ float g_bias[3 * 2 * G4];                       // b_ih + b_hh combined
__device__ float g_wt[(size_t)3 * 2 * 8 * 32768];          // w_hh re-tiled per (l,d,ugi)
__device__ float g_energy[(size_t)TT * BBATCH];            // energy then softmax weights
__device__ float g_feats[(size_t)BBATCH * TT * NTAGS];     // [b][t][tag]
__device__ unsigned int g_flag2[128];                      // [d*64 + bg*8 + ugi] step flags
// bf16 hi/lo split buffers for tensor-core GEMM
__device__ __nv_bfloat16 g_ah[(size_t)TT * BBATCH * EE];   // A hi
__device__ __nv_bfloat16 g_al[(size_t)TT * BBATCH * EE];   // A lo
#define WSPLIT_N (3 * 2 * G4 * EE + 512 * 512)             // w_ih (all) + aw1
__device__ __nv_bfloat16 g_wh2[WSPLIT_N];
__device__ __nv_bfloat16 g_wl2[WSPLIT_N];

// ---------------- f32x2 packed-FMA helpers ----------------
__device__ __forceinline__ void ffma2(unsigned long long& d, unsigned long long a,
                                      unsigned long long b) {
    asm("fma.rn.f32x2 %0, %1, %2, %0;" : "+l"(d) : "l"(a), "l"(b));
}
__device__ __forceinline__ unsigned long long pack2(float x, float y) {
    unsigned long long r;
    asm("mov.b64 %0, {%1, %2};" : "=l"(r) : "f"(x), "f"(y));
    return r;
}
__device__ __forceinline__ void unpack2(float& x, float& y, unsigned long long v) {
    asm("mov.b64 {%0, %1}, %2;" : "=f"(x), "=f"(y) : "l"(v));
}

// ---------------- tiny utility kernels ----------------
__global__ void zero_out_kernel(float* out) { out[0] = 0.f; }

__global__ void bias_kernel(const float* __restrict__ b_ih, const float* __restrict__ b_hh) {
    int i = blockIdx.x * blockDim.x + threadIdx.x;
    if (i < 3 * 2 * G4) g_bias[i] = b_ih[i] + b_hh[i];
}

__global__ void zero_state_kernel() {
    int i = blockIdx.x * blockDim.x + threadIdx.x;
    if (i < 2 * 2 * 8 * 2048) g_hb[i] = 0.f;
    if (i < 128) g_flag2[i] = 0u;
}

// Re-tile w_hh (3,2,1024,256) into g_wt[(l,d,ugi)][k][up][g][usel]
__global__ void wt_kernel(const float* __restrict__ whh) {
    size_t i = (size_t)blockIdx.x * blockDim.x + threadIdx.x;
    const size_t n = (size_t)3 * 2 * 8 * 32768;
    if (i >= n) return;
    int usel = i & 1;
    int g    = (i >> 1) & 3;
    int up   = (i >> 3) & 15;
    int k    = (i >> 7) & 255;
    int ugi  = (i >> 15) & 7;
    int ld   = (int)(i >> 18);
    int u = ugi * 32 + up * 2 + usel;
    g_wt[i] = whh[((size_t)ld * G4 + g * 256 + u) * HH + k];
}

// gather embeddings -> g_x[t][b][e]
__global__ void embed_kernel(const int* __restrict__ sent, const float* __restrict__ emb) {
    size_t i = (size_t)blockIdx.x * blockDim.x + threadIdx.x;
    const size_t n = (size_t)TT * BBATCH * EE;
    if (i >= n) return;
    int e = i & (EE - 1);
    size_t r = i >> 9;
    int b = r & (BBATCH - 1);
    int t = (int)(r >> 6);
    g_x[i] = emb[(size_t)sent[b * TT + t] * EE + e];
}

// split fp32 -> bf16 hi/lo (x = hi + lo to ~17-bit mantissa), 4 elems/thread
__global__ void cvt_split_kernel(const float* __restrict__ src,
                                 __nv_bfloat16* __restrict__ hi,
                                 __nv_bfloat16* __restrict__ lo, int n4) {
    int i = blockIdx.x * blockDim.x + threadIdx.x;
    if (i >= n4) return;
    float4 v = ((const float4*)src)[i];
    __nv_bfloat16 h0 = __float2bfloat16(v.x), h1 = __float2bfloat16(v.y);
    __nv_bfloat16 h2 = __float2bfloat16(v.z), h3 = __float2bfloat16(v.w);
    __nv_bfloat162 hh0, hh1, ll0, ll1;
    hh0.x = h0; hh0.y = h1; hh1.x = h2; hh1.y = h3;
    ll0.x = __float2bfloat16(v.x - __bfloat162float(h0));
    ll0.y = __float2bfloat16(v.y - __bfloat162float(h1));
    ll1.x = __float2bfloat16(v.z - __bfloat162float(h2));
    ll1.y = __float2bfloat16(v.w - __bfloat162float(h3));
    ((__nv_bfloat162*)hi)[2 * i] = hh0; ((__nv_bfloat162*)hi)[2 * i + 1] = hh1;
    ((__nv_bfloat162*)lo)[2 * i] = ll0; ((__nv_bfloat162*)lo)[2 * i + 1] = ll1;
}

// ---------------- tensor-core GEMM (bf16 hi/lo split, fp32 accum) ----------------
// C[M,N] = A[M,K] @ W[N,K]^T + bias[N]; M,N mult of 128, K mult of 16.
// 128x128 block tile, 8 warps, each 64x32 (4x4 m16n8k16 tiles), 3 split products.
__device__ __forceinline__ void ldsm4(uint32_t* r, uint32_t addr) {
    asm volatile("ldmatrix.sync.aligned.m8n8.x4.shared.b16 {%0,%1,%2,%3}, [%4];"
                 : "=r"(r[0]), "=r"(r[1]), "=r"(r[2]), "=r"(r[3]) : "r"(addr));
}
__device__ __forceinline__ void ldsm2(uint32_t* r, uint32_t addr) {
    asm volatile("ldmatrix.sync.aligned.m8n8.x2.shared.b16 {%0,%1}, [%2];"
                 : "=r"(r[0]), "=r"(r[1]) : "r"(addr));
}
__device__ __forceinline__ void mma_bf16(float* d, const uint32_t* a, const uint32_t* b) {
    asm volatile(
        "mma.sync.aligned.m16n8k16.row.col.f32.bf16.bf16.f32 "
        "{%0,%1,%2,%3}, {%4,%5,%6,%7}, {%8,%9}, {%0,%1,%2,%3};"
        : "+f"(d[0]), "+f"(d[1]), "+f"(d[2]), "+f"(d[3])
        : "r"(a[0]), "r"(a[1]), "r"(a[2]), "r"(a[3]), "r"(b[0]), "r"(b[1]));
}

#define GLDK 24   // padded smem k-stride (48B): ldmatrix conflict-free

__global__ __launch_bounds__(256) void gemm_tc_kernel(
    const __nv_bfloat16* __restrict__ Ah, const __nv_bfloat16* __restrict__ Al,
    const __nv_bfloat16* __restrict__ Wh, const __nv_bfloat16* __restrict__ Wl,
    const float* __restrict__ bias, float* __restrict__ C,
    int M, int N, int K)
{
    __shared__ __nv_bfloat16 sA[2][2][128][GLDK];
    __shared__ __nv_bfloat16 sW[2][2][128][GLDK];
    const int tid = threadIdx.x;
    const int bm = blockIdx.y * 128, bn = blockIdx.x * 128;
    const int row = tid >> 1, half = tid & 1;
    const int lane = tid & 31, wid = tid >> 5;
    const int wm = (wid >> 2) * 64, wn = (wid & 3) * 32;

    const __nv_bfloat16* gAh = Ah + (size_t)(bm + row) * K + half * 8;
    const __nv_bfloat16* gAl = Al + (size_t)(bm + row) * K + half * 8;
    const __nv_bfloat16* gWh = Wh + (size_t)(bn + row) * K + half * 8;
    const __nv_bfloat16* gWl = Wl + (size_t)(bn + row) * K + half * 8;

    float acc[4][4][4];
#pragma unroll
    for (int i = 0; i < 4; i++)
#pragma unroll
        for (int j = 0; j < 4; j++)
#pragma unroll
            for (int r = 0; r < 4; r++) acc[i][j][r] = 0.f;

    // ldmatrix source addresses (per lane)
    uint32_t aBase[2], wBase[2];
    {
        int ar = (lane & 15), ac = (lane >> 4) * 8;
        int wr = (lane & 7), wc = ((lane >> 3) & 1) * 8;
        aBase[0] = (uint32_t)__cvta_generic_to_shared(&sA[0][0][ar][ac]);
        aBase[1] = (uint32_t)__cvta_generic_to_shared(&sA[1][0][ar][ac]);
        wBase[0] = (uint32_t)__cvta_generic_to_shared(&sW[0][0][wr][wc]);
        wBase[1] = (uint32_t)__cvta_generic_to_shared(&sW[1][0][wr][wc]);
    }
    const uint32_t HILO = 128 * GLDK * 2;      // bytes between hi and lo planes
    const uint32_t ROW16 = 16 * GLDK * 2;      // 16 rows
    const uint32_t ROW8 = 8 * GLDK * 2;

    // prologue: stage 0
    {
        uint4 va = *(const uint4*)gAh, vb = *(const uint4*)gAl;
        uint4 vc = *(const uint4*)gWh, vd = *(const uint4*)gWl;
        *(uint4*)&sA[0][0][row][half * 8] = va;
        *(uint4*)&sA[0][1][row][half * 8] = vb;
        *(uint4*)&sW[0][0][row][half * 8] = vc;
        *(uint4*)&sW[0][1][row][half * 8] = vd;
    }
    __syncthreads();

    const int nk = K >> 4;
    for (int ch = 0; ch < nk; ch++) {
        const int cur = ch & 1, nxt = cur ^ 1;
        uint4 va, vb, vc, vd;
        if (ch + 1 < nk) {
            int off = (ch + 1) * 16;
            va = *(const uint4*)(gAh + off); vb = *(const uint4*)(gAl + off);
            vc = *(const uint4*)(gWh + off); vd = *(const uint4*)(gWl + off);
        }

        // fragments
        uint32_t ah[4][4], al[4][4], wh[4][2], wl[4][2];
        uint32_t aAddr = aBase[cur] + wm * (GLDK * 2);
        uint32_t wAddr = wBase[cur] + wn * (GLDK * 2);
#pragma unroll
        for (int mt = 0; mt < 4; mt++) {
            ldsm4(ah[mt], aAddr + mt * ROW16);
            ldsm4(al[mt], aAddr + mt * ROW16 + HILO);
        }
#pragma unroll
        for (int nt = 0; nt < 4; nt++) {
            ldsm2(wh[nt], wAddr + nt * ROW8);
            ldsm2(wl[nt], wAddr + nt * ROW8 + HILO);
        }
#pragma unroll
        for (int mt = 0; mt < 4; mt++)
#pragma unroll
            for (int nt = 0; nt < 4; nt++) {
                mma_bf16(acc[mt][nt], ah[mt], wh[nt]);
                mma_bf16(acc[mt][nt], ah[mt], wl[nt]);
                mma_bf16(acc[mt][nt], al[mt], wh[nt]);
            }

        if (ch + 1 < nk) {
            *(uint4*)&sA[nxt][0][row][half * 8] = va;
            *(uint4*)&sA[nxt][1][row][half * 8] = vb;
            *(uint4*)&sW[nxt][0][row][half * 8] = vc;
            *(uint4*)&sW[nxt][1][row][half * 8] = vd;
        }
        __syncthreads();
    }

    // epilogue: C = acc + bias
    const int g = lane >> 2, q = lane & 3;
#pragma unroll
    for (int mt = 0; mt < 4; mt++)
#pragma unroll
        for (int nt = 0; nt < 4; nt++) {
            int r0 = bm + wm + mt * 16 + g;
            int c0 = bn + wn + nt * 8 + q * 2;
            float b0v = bias[c0], b1v = bias[c0 + 1];
            float2 o0, o1;
            o0.x = acc[mt][nt][0] + b0v; o0.y = acc[mt][nt][1] + b1v;
            o1.x = acc[mt][nt][2] + b0v; o1.y = acc[mt][nt][3] + b1v;
            *(float2*)&C[(size_t)r0 * N + c0] = o0;
            *(float2*)&C[(size_t)(r0 + 8) * N + c0] = o1;
        }
}

// ---------------- persistent LSTM layer kernel (unchanged from R4) ----------------
__global__ __launch_bounds__(128) void lstm_layer_kernel(
    const float* __restrict__ wt_l,
    const float* __restrict__ pre,
    float* __restrict__ out)
{
    extern __shared__ float sm[];
    float* ws = sm;              // 32768 floats
    float* hs = sm + 32768;      // 2048 floats
    const int bi  = blockIdx.x;
    const int d   = bi >> 6;
    const int bg  = (bi >> 3) & 7;
    const int ugi = bi & 7;
    const int tid = threadIdx.x;
    const int b   = tid & 7;
    const int up  = tid >> 3;
    const int u0  = ugi * 32 + up * 2;
    const int bglob = bg * 8 + b;

    const float4* wsrc = (const float4*)(wt_l + ((size_t)(d * 8 + ugi)) * 32768);
    float4* ws4 = (float4*)ws;
    for (int i = tid; i < 8192; i += 128) ws4[i] = wsrc[i];

    unsigned int* flags = &g_flag2[d * 64 + bg * 8];
    float4* hs4 = (float4*)hs;
    float c0 = 0.f, c1 = 0.f;

    for (int s = 0; s < TT; s++) {
        const int tt = d ? (TT - 1 - s) : s;
        const int rp = s & 1, wp = rp ^ 1;

        const float* prow = pre + ((size_t)tt * BBATCH + bglob) * 2048 + d * G4;
        float p[8];
#pragma unroll
        for (int g = 0; g < 4; g++) {
            float2 pv = *(const float2*)&prow[g * 256 + u0];
            p[2 * g] = pv.x; p[2 * g + 1] = pv.y;
        }

        if (s) {
            if (tid < 8) {
                const unsigned int* fp = flags + tid;
                unsigned int v;
                do {
                    asm volatile("ld.acquire.gpu.global.u32 %0, [%1];"
                                 : "=r"(v) : "l"(fp) : "memory");
                } while (v < (unsigned int)s);
            }
            __syncthreads();
        }

        const float4* hsrc = (const float4*)(g_hb + (((size_t)rp * 2 + d) * 8 + bg) * 2048);
#pragma unroll
        for (int i = tid; i < 512; i += 128) hs4[i] = __ldcg(hsrc + i);
        __syncthreads();

        unsigned long long a0 = 0ull, a1 = 0ull, a2 = 0ull, a3 = 0ull;
        const float* wbase = ws + up * 8;
#pragma unroll 8
        for (int k = 0; k < 256; k++) {
            float hv = hs[k * 8 + b];
            unsigned long long hh = pack2(hv, hv);
            const float* wk = wbase + k * 128;
            ulonglong2 w01 = *(const ulonglong2*)(wk);
            ulonglong2 w23 = *(const ulonglong2*)(wk + 4);
            ffma2(a0, hh, w01.x); ffma2(a1, hh, w01.y);
            ffma2(a2, hh, w23.x); ffma2(a3, hh, w23.y);
        }
        float i0, i1, f0, f1, gg0, gg1, o0, o1;
        unpack2(i0, i1, a0); unpack2(f0, f1, a1);
        unpack2(gg0, gg1, a2); unpack2(o0, o1, a3);

        float gi0 = p[0] + i0, gf0 = p[2] + f0, gg0v = p[4] + gg0, go0 = p[6] + o0;
        float gi1 = p[1] + i1, gf1 = p[3] + f1, gg1v = p[5] + gg1, go1 = p[7] + o1;
        float iv0 = 1.f / (1.f + expf(-gi0));
        float fv0 = 1.f / (1.f + expf(-gf0));
        float gv0 = tanhf(gg0v);
        float ov0 = 1.f / (1.f + expf(-go0));
        c0 = fv0 * c0 + iv0 * gv0;
        float h0 = ov0 * tanhf(c0);
        float iv1 = 1.f / (1.f + expf(-gi1));
        float fv1 = 1.f / (1.f + expf(-gf1));
        float gv1 = tanhf(gg1v);
        float ov1 = 1.f / (1.f + expf(-go1));
        c1 = fv1 * c1 + iv1 * gv1;
        float h1 = ov1 * tanhf(c1);

        float* hdst = g_hb + (((size_t)wp * 2 + d) * 8 + bg) * 2048;
        hdst[u0 * 8 + b]       = h0;
        hdst[(u0 + 1) * 8 + b] = h1;
        float2 ho; ho.x = h0; ho.y = h1;
        *(float2*)(out + ((size_t)tt * BBATCH + bglob) * HD2 + d * HH + u0) = ho;

        __syncthreads();
        if (tid == 0) {
            asm volatile("st.release.gpu.global.u32 [%0], %1;"
                         :: "l"(flags + ugi), "r"((unsigned int)(s + 1)) : "memory");
        }
    }
}

// ---------------- attention ----------------
__global__ __launch_bounds__(256) void energy_kernel(const float* __restrict__ z,
                                                     const float* __restrict__ aw2,
                                                     const float* __restrict__ ab2)
{
    int w = threadIdx.x >> 5, lane = threadIdx.x & 31;
    int r = blockIdx.x * 8 + w;
    const float* zr = z + (size_t)r * 512;
    float acc = 0.f;
#pragma unroll
    for (int j = 0; j < 16; j++) {
        int k = lane + j * 32;
        acc += tanhf(zr[k]) * aw2[k];
    }
#pragma unroll
    for (int o = 16; o > 0; o >>= 1) acc += __shfl_down_sync(0xffffffffu, acc, o);
    if (lane == 0) g_energy[r] = acc + ab2[0];
}

__global__ __launch_bounds__(256) void softmax_kernel() {
    __shared__ float red[256];
    int b = blockIdx.x, t = threadIdx.x;
    float e = g_energy[t * 64 + b];
    red[t] = e;
    __syncthreads();
    for (int s = 128; s > 0; s >>= 1) {
        if (t < s) red[t] = fmaxf(red[t], red[t + s]);
        __syncthreads();
    }
    float m = red[0];
    __syncthreads();
    float p = expf(e - m);
    red[t] = p;
    __syncthreads();
    for (int s = 128; s > 0; s >>= 1) {
        if (t < s) red[t] += red[t + s];
        __syncthreads();
    }
    g_energy[t * 64 + b] = p / red[0];
}

__global__ __launch_bounds__(256) void feats_kernel(const float* __restrict__ y,
                                                    const float* __restrict__ hw,
                                                    const float* __restrict__ hb)
{
    int w = threadIdx.x >> 5, lane = threadIdx.x & 31;
    int r = blockIdx.x * 8 + w;
    const float* yr = y + (size_t)r * 512;
    float acc[NTAGS];
#pragma unroll
    for (int i = 0; i < NTAGS; i++) acc[i] = 0.f;
#pragma unroll
    for (int j = 0; j < 16; j++) {
        int k = lane + j * 32;
        float v = yr[k];
#pragma unroll
        for (int i = 0; i < NTAGS; i++) acc[i] += v * hw[i * 512 + k];
    }
#pragma unroll
    for (int i = 0; i < NTAGS; i++)
#pragma unroll
        for (int o = 16; o > 0; o >>= 1) acc[i] += __shfl_down_sync(0xffffffffu, acc[i], o);
    if (lane == 0) {
        float wt = 1.f + g_energy[r];
        int b = r & 63, t = r >> 6;
#pragma unroll
        for (int i = 0; i < NTAGS; i++)
            g_feats[((size_t)b * TT + t) * NTAGS + i] = wt * acc[i] + hb[i];
    }
}

// ---------------- CRF ----------------
__global__ __launch_bounds__(32) void crf_kernel(const int* __restrict__ tags,
                                                 const float* __restrict__ mask,
                                                 const float* __restrict__ trans,
                                                 float* __restrict__ out)
{
    __shared__ float tr[36];
    int b = blockIdx.x, lid = threadIdx.x;
    for (int i = lid; i < 36; i += 32) tr[i] = trans[i];
    __syncwarp();

    const int ii = lid % NTAGS;
    const float* fb = g_feats + (size_t)b * TT * NTAGS;
    const float* mb = mask + (size_t)b * TT;

    float fv = (ii == TAG_START) ? 0.f : NEGV;
    for (int t = 0; t < TT; t++) {
        float fj[NTAGS];
#pragma unroll
        for (int j = 0; j < NTAGS; j++) fj[j] = __shfl_sync(0xffffffffu, fv, j);
        float v[NTAGS];
        float m = -3.4e38f;
#pragma unroll
        for (int j = 0; j < NTAGS; j++) {
            v[j] = fj[j] + tr[ii * NTAGS + j];
            m = fmaxf(m, v[j]);
        }
        float ssum = 0.f;
#pragma unroll
        for (int j = 0; j < NTAGS; j++) ssum += expf(v[j] - m);
        float nxt = m + logf(ssum) + fb[t * NTAGS + ii];
        fv = (mb[t] > 0.f) ? nxt : fv;
    }
    float sv = fv + tr[TAG_STOP * NTAGS + ii];
    float gvals[NTAGS];
#pragma unroll
    for (int j = 0; j < NTAGS; j++) gvals[j] = __shfl_sync(0xffffffffu, sv, j);
    float m2 = -3.4e38f;
#pragma unroll
    for (int j = 0; j < NTAGS; j++) m2 = fmaxf(m2, gvals[j]);
    float s2 = 0.f;
#pragma unroll
    for (int j = 0; j < NTAGS; j++) s2 += expf(gvals[j] - m2);
    float fwd = m2 + logf(s2);

    float gold = 0.f, msum = 0.f;
    for (int t = lid; t < TT; t += 32) {
        int cur = tags[b * TT + t];
        int prev = t ? tags[b * TT + t - 1] : TAG_START;
        float mm = mb[t];
        gold += (fb[t * NTAGS + cur] + tr[cur * NTAGS + prev]) * mm;
        msum += mm;
    }
#pragma unroll
    for (int o = 16; o > 0; o >>= 1) {
        gold += __shfl_down_sync(0xffffffffu, gold, o);
        msum += __shfl_down_sync(0xffffffffu, msum, o);
    }
    if (lid == 0) {
        int sl = (int)(msum + 0.5f);
        int last = (sl > 0) ? tags[b * TT + sl - 1] : TAG_START;
        gold += tr[TAG_STOP * NTAGS + last];
        atomicAdd(out, (fwd - gold) * (1.f / 64.f));
    }
}

// ---------------- launch ----------------
extern "C" void kernel_launch(void* const* d_in, const int* in_sizes, int n_in,
                              void* d_out, int out_size)
{
    const int*   sentences = (const int*)d_in[0];
    const int*   tags      = (const int*)d_in[1];
    const float* mask      = (const float*)d_in[2];
    const float* embed     = (const float*)d_in[3];
    const float* w_ih      = (const float*)d_in[4];
    const float* w_hh      = (const float*)d_in[5];
    const float* b_ih      = (const float*)d_in[6];
    const float* b_hh      = (const float*)d_in[7];
    const float* aw1       = (const float*)d_in[8];
    const float* ab1       = (const float*)d_in[9];
    const float* aw2       = (const float*)d_in[10];
    const float* ab2       = (const float*)d_in[11];
    const float* hw        = (const float*)d_in[12];
    const float* hb        = (const float*)d_in[13];
    const float* trans     = (const float*)d_in[14];
    float* out = (float*)d_out;

    const int STEP_SMEM = (32768 + 2048) * 4;  // 136 KB
    cudaFuncSetAttribute(lstm_layer_kernel, cudaFuncAttributeMaxDynamicSharedMemorySize, STEP_SMEM);

    zero_out_kernel<<<1, 1>>>(out);
    bias_kernel<<<24, 256>>>(b_ih, b_hh);
    wt_kernel<<<6144, 256>>>(w_hh);
    embed_kernel<<<32768, 256>>>(sentences, embed);

    float *px, *py, *ppre, *pbias, *pwt;
    __nv_bfloat16 *pah, *pal, *pwh2, *pwl2;
    cudaGetSymbolAddress((void**)&px, g_x);
    cudaGetSymbolAddress((void**)&py, g_y);
    cudaGetSymbolAddress((void**)&ppre, g_pre);
    cudaGetSymbolAddress((void**)&pbias, g_bias);
    cudaGetSymbolAddress((void**)&pwt, g_wt);
    cudaGetSymbolAddress((void**)&pah, g_ah);
    cudaGetSymbolAddress((void**)&pal, g_al);
    cudaGetSymbolAddress((void**)&pwh2, g_wh2);
    cudaGetSymbolAddress((void**)&pwl2, g_wl2);

    const int M = TT * BBATCH;        // 16384
    const int NA = M * EE;            // 8388608
    const int NWIH = 3 * 2 * G4 * EE; // 3145728

    // split w_ih (all layers) and aw1 into bf16 hi/lo
    cvt_split_kernel<<<NWIH / 4 / 256, 256>>>(w_ih, pwh2, pwl2, NWIH / 4);
    cvt_split_kernel<<<512 * 512 / 4 / 256, 256>>>(aw1, pwh2 + NWIH, pwl2 + NWIH, 512 * 512 / 4);

    float* lin = px;
    float* lout = py;
    for (int l = 0; l < 3; l++) {
        zero_state_kernel<<<256, 256>>>();
        cvt_split_kernel<<<NA / 4 / 256, 256>>>(lin, pah, pal, NA / 4);
        dim3 g1(2048 / 128, M / 128);
        gemm_tc_kernel<<<g1, 256>>>(pah, pal,
                                    pwh2 + (size_t)l * 2 * G4 * EE,
                                    pwl2 + (size_t)l * 2 * G4 * EE,
                                    pbias + l * 2048, ppre, M, 2048, EE);
        const float* wtl = pwt + (size_t)l * 2 * 8 * 32768;
        lstm_layer_kernel<<<128, 128, STEP_SMEM>>>(wtl, ppre, lout);
        float* tmp = lin; lin = lout; lout = tmp;
    }
    float* lstm_out = lin;   // == py
    float* zbuf = lout;      // == px

    cvt_split_kernel<<<NA / 4 / 256, 256>>>(lstm_out, pah, pal, NA / 4);
    dim3 g2(512 / 128, M / 128);
    gemm_tc_kernel<<<g2, 256>>>(pah, pal, pwh2 + NWIH, pwl2 + NWIH,
                                ab1, zbuf, M, 512, EE);
    energy_kernel<<<M / 8, 256>>>(zbuf, aw2, ab2);
    softmax_kernel<<<BBATCH, 256>>>();
    feats_kernel<<<M / 8, 256>>>(lstm_out, hw, hb);
    crf_kernel<<<BBATCH, 32>>>(tags, mask, trans, out);
}

// round 7
// speedup vs baseline: 2.6786x; 1.4336x over previous
#include <cuda_runtime.h>
#include <cuda_bf16.h>
#include <math.h>
#include <stdint.h>

// Problem constants
#define TT 256      // T
#define BBATCH 64   // B
#define EE 512      // E (= input dim for ALL layers, since 2H = 512)
#define HH 256      // H
#define G4 1024     // 4H
#define HD2 512     // 2H
#define NTAGS 6
#define TAG_START 4
#define TAG_STOP 5
#define NEGV -1000000.0f

typedef unsigned long long ull;

// ---------------- device scratch (static allocations only) ----------------
__device__ float g_x[(size_t)TT * BBATCH * EE];            // layer input / z buffer
__device__ float g_y[(size_t)TT * BBATCH * EE];            // layer output / lstm_out
__device__ float g_pre[(size_t)TT * BBATCH * 2048];        // (t,b,[dir0 1024 | dir1 1024])
__device__ float g_hb[2 * 2 * 8 * 2048];                   // [parity][dir][bg][u*8+b] h-state
__device__ float g_bias[3 * 2 * G4];                       // b_ih + b_hh combined
__device__ float g_wt[(size_t)3 * 2 * 8 * 32768];          // w_hh re-tiled per (l,d,ugi,u_in,kq,kk,g)
__device__ float g_energy[(size_t)TT * BBATCH];            // energy then softmax weights
__device__ float g_feats[(size_t)BBATCH * TT * NTAGS];     // [b][t][tag]
__device__ unsigned int g_flag2[128];                      // [d*64 + bg*8 + ugi] step flags
// bf16 hi/lo split buffers for tensor-core GEMM
__device__ __nv_bfloat16 g_ah[(size_t)TT * BBATCH * EE];   // A hi
__device__ __nv_bfloat16 g_al[(size_t)TT * BBATCH * EE];   // A lo
#define WSPLIT_N (3 * 2 * G4 * EE + 512 * 512)             // w_ih (all) + aw1
__device__ __nv_bfloat16 g_wh2[WSPLIT_N];
__device__ __nv_bfloat16 g_wl2[WSPLIT_N];

// ---------------- f32x2 packed-FMA helpers ----------------
__device__ __forceinline__ void ffma2(ull& d, ull a, ull b) {
    asm("fma.rn.f32x2 %0, %1, %2, %0;" : "+l"(d) : "l"(a), "l"(b));
}
__device__ __forceinline__ ull addx2(ull a, ull b) {
    ull r;
    asm("add.rn.f32x2 %0, %1, %2;" : "=l"(r) : "l"(a), "l"(b));
    return r;
}
__device__ __forceinline__ ull pack2(float x, float y) {
    ull r;
    asm("mov.b64 %0, {%1, %2};" : "=l"(r) : "f"(x), "f"(y));
    return r;
}
__device__ __forceinline__ void unpack2(float& x, float& y, ull v) {
    asm("mov.b64 {%0, %1}, %2;" : "=f"(x), "=f"(y) : "l"(v));
}

// ---------------- tiny utility kernels ----------------
__global__ void zero_out_kernel(float* out) { out[0] = 0.f; }

__global__ void bias_kernel(const float* __restrict__ b_ih, const float* __restrict__ b_hh) {
    int i = blockIdx.x * blockDim.x + threadIdx.x;
    if (i < 3 * 2 * G4) g_bias[i] = b_ih[i] + b_hh[i];
}

__global__ void zero_state_kernel() {
    int i = blockIdx.x * blockDim.x + threadIdx.x;
    if (i < 2 * 2 * 8 * 2048) g_hb[i] = 0.f;
    if (i < 128) g_flag2[i] = 0u;
}

// Re-tile w_hh (3,2,1024,256) into g_wt[l][d][ugi][u_in][kq][kk][g]
// u = ugi*32 + u_in, k = kq*32 + kk, gate g in {i,f,g,o}
__global__ void wt_kernel(const float* __restrict__ whh) {
    size_t i = (size_t)blockIdx.x * blockDim.x + threadIdx.x;
    const size_t n = (size_t)3 * 2 * 8 * 32768;
    if (i >= n) return;
    int g    = i & 3;
    int kk   = (i >> 2) & 31;
    int kq   = (i >> 7) & 7;
    int u_in = (i >> 10) & 31;
    int ugi  = (i >> 15) & 7;
    int ld   = (int)(i >> 18);   // l*2 + d
    int u = ugi * 32 + u_in;
    int k = kq * 32 + kk;
    g_wt[i] = whh[((size_t)ld * G4 + g * 256 + u) * HH + k];
}

// gather embeddings -> g_x[t][b][e]
__global__ void embed_kernel(const int* __restrict__ sent, const float* __restrict__ emb) {
    size_t i = (size_t)blockIdx.x * blockDim.x + threadIdx.x;
    const size_t n = (size_t)TT * BBATCH * EE;
    if (i >= n) return;
    int e = i & (EE - 1);
    size_t r = i >> 9;
    int b = r & (BBATCH - 1);
    int t = (int)(r >> 6);
    g_x[i] = emb[(size_t)sent[b * TT + t] * EE + e];
}

// split fp32 -> bf16 hi/lo (x = hi + lo to ~17-bit mantissa), 4 elems/thread
__global__ void cvt_split_kernel(const float* __restrict__ src,
                                 __nv_bfloat16* __restrict__ hi,
                                 __nv_bfloat16* __restrict__ lo, int n4) {
    int i = blockIdx.x * blockDim.x + threadIdx.x;
    if (i >= n4) return;
    float4 v = ((const float4*)src)[i];
    __nv_bfloat16 h0 = __float2bfloat16(v.x), h1 = __float2bfloat16(v.y);
    __nv_bfloat16 h2 = __float2bfloat16(v.z), h3 = __float2bfloat16(v.w);
    __nv_bfloat162 hh0, hh1, ll0, ll1;
    hh0.x = h0; hh0.y = h1; hh1.x = h2; hh1.y = h3;
    ll0.x = __float2bfloat16(v.x - __bfloat162float(h0));
    ll0.y = __float2bfloat16(v.y - __bfloat162float(h1));
    ll1.x = __float2bfloat16(v.z - __bfloat162float(h2));
    ll1.y = __float2bfloat16(v.w - __bfloat162float(h3));
    ((__nv_bfloat162*)hi)[2 * i] = hh0; ((__nv_bfloat162*)hi)[2 * i + 1] = hh1;
    ((__nv_bfloat162*)lo)[2 * i] = ll0; ((__nv_bfloat162*)lo)[2 * i + 1] = ll1;
}

// ---------------- tensor-core GEMM (bf16 hi/lo split, fp32 accum) ----------------
__device__ __forceinline__ void ldsm4(uint32_t* r, uint32_t addr) {
    asm volatile("ldmatrix.sync.aligned.m8n8.x4.shared.b16 {%0,%1,%2,%3}, [%4];"
                 : "=r"(r[0]), "=r"(r[1]), "=r"(r[2]), "=r"(r[3]) : "r"(addr));
}
__device__ __forceinline__ void ldsm2(uint32_t* r, uint32_t addr) {
    asm volatile("ldmatrix.sync.aligned.m8n8.x2.shared.b16 {%0,%1}, [%2];"
                 : "=r"(r[0]), "=r"(r[1]) : "r"(addr));
}
__device__ __forceinline__ void mma_bf16(float* d, const uint32_t* a, const uint32_t* b) {
    asm volatile(
        "mma.sync.aligned.m16n8k16.row.col.f32.bf16.bf16.f32 "
        "{%0,%1,%2,%3}, {%4,%5,%6,%7}, {%8,%9}, {%0,%1,%2,%3};"
        : "+f"(d[0]), "+f"(d[1]), "+f"(d[2]), "+f"(d[3])
        : "r"(a[0]), "r"(a[1]), "r"(a[2]), "r"(a[3]), "r"(b[0]), "r"(b[1]));
}

#define GLDK 24   // padded smem k-stride (48B): ldmatrix conflict-free

__global__ __launch_bounds__(256) void gemm_tc_kernel(
    const __nv_bfloat16* __restrict__ Ah, const __nv_bfloat16* __restrict__ Al,
    const __nv_bfloat16* __restrict__ Wh, const __nv_bfloat16* __restrict__ Wl,
    const float* __restrict__ bias, float* __restrict__ C,
    int M, int N, int K)
{
    __shared__ __nv_bfloat16 sA[2][2][128][GLDK];
    __shared__ __nv_bfloat16 sW[2][2][128][GLDK];
    const int tid = threadIdx.x;
    const int bm = blockIdx.y * 128, bn = blockIdx.x * 128;
    const int row = tid >> 1, half = tid & 1;
    const int lane = tid & 31, wid = tid >> 5;
    const int wm = (wid >> 2) * 64, wn = (wid & 3) * 32;

    const __nv_bfloat16* gAh = Ah + (size_t)(bm + row) * K + half * 8;
    const __nv_bfloat16* gAl = Al + (size_t)(bm + row) * K + half * 8;
    const __nv_bfloat16* gWh = Wh + (size_t)(bn + row) * K + half * 8;
    const __nv_bfloat16* gWl = Wl + (size_t)(bn + row) * K + half * 8;

    float acc[4][4][4];
#pragma unroll
    for (int i = 0; i < 4; i++)
#pragma unroll
        for (int j = 0; j < 4; j++)
#pragma unroll
            for (int r = 0; r < 4; r++) acc[i][j][r] = 0.f;

    uint32_t aBase[2], wBase[2];
    {
        int ar = (lane & 15), ac = (lane >> 4) * 8;
        int wr = (lane & 7), wc = ((lane >> 3) & 1) * 8;
        aBase[0] = (uint32_t)__cvta_generic_to_shared(&sA[0][0][ar][ac]);
        aBase[1] = (uint32_t)__cvta_generic_to_shared(&sA[1][0][ar][ac]);
        wBase[0] = (uint32_t)__cvta_generic_to_shared(&sW[0][0][wr][wc]);
        wBase[1] = (uint32_t)__cvta_generic_to_shared(&sW[1][0][wr][wc]);
    }
    const uint32_t HILO = 128 * GLDK * 2;
    const uint32_t ROW16 = 16 * GLDK * 2;
    const uint32_t ROW8 = 8 * GLDK * 2;

    {
        uint4 va = *(const uint4*)gAh, vb = *(const uint4*)gAl;
        uint4 vc = *(const uint4*)gWh, vd = *(const uint4*)gWl;
        *(uint4*)&sA[0][0][row][half * 8] = va;
        *(uint4*)&sA[0][1][row][half * 8] = vb;
        *(uint4*)&sW[0][0][row][half * 8] = vc;
        *(uint4*)&sW[0][1][row][half * 8] = vd;
    }
    __syncthreads();

    const int nk = K >> 4;
    for (int ch = 0; ch < nk; ch++) {
        const int cur = ch & 1, nxt = cur ^ 1;
        uint4 va, vb, vc, vd;
        if (ch + 1 < nk) {
            int off = (ch + 1) * 16;
            va = *(const uint4*)(gAh + off); vb = *(const uint4*)(gAl + off);
            vc = *(const uint4*)(gWh + off); vd = *(const uint4*)(gWl + off);
        }

        uint32_t ah[4][4], al[4][4], wh[4][2], wl[4][2];
        uint32_t aAddr = aBase[cur] + wm * (GLDK * 2);
        uint32_t wAddr = wBase[cur] + wn * (GLDK * 2);
#pragma unroll
        for (int mt = 0; mt < 4; mt++) {
            ldsm4(ah[mt], aAddr + mt * ROW16);
            ldsm4(al[mt], aAddr + mt * ROW16 + HILO);
        }
#pragma unroll
        for (int nt = 0; nt < 4; nt++) {
            ldsm2(wh[nt], wAddr + nt * ROW8);
            ldsm2(wl[nt], wAddr + nt * ROW8 + HILO);
        }
#pragma unroll
        for (int mt = 0; mt < 4; mt++)
#pragma unroll
            for (int nt = 0; nt < 4; nt++) {
                mma_bf16(acc[mt][nt], ah[mt], wh[nt]);
                mma_bf16(acc[mt][nt], ah[mt], wl[nt]);
                mma_bf16(acc[mt][nt], al[mt], wh[nt]);
            }

        if (ch + 1 < nk) {
            *(uint4*)&sA[nxt][0][row][half * 8] = va;
            *(uint4*)&sA[nxt][1][row][half * 8] = vb;
            *(uint4*)&sW[nxt][0][row][half * 8] = vc;
            *(uint4*)&sW[nxt][1][row][half * 8] = vd;
        }
        __syncthreads();
    }

    const int g = lane >> 2, q = lane & 3;
#pragma unroll
    for (int mt = 0; mt < 4; mt++)
#pragma unroll
        for (int nt = 0; nt < 4; nt++) {
            int r0 = bm + wm + mt * 16 + g;
            int c0 = bn + wn + nt * 8 + q * 2;
            float b0v = bias[c0], b1v = bias[c0 + 1];
            float2 o0, o1;
            o0.x = acc[mt][nt][0] + b0v; o0.y = acc[mt][nt][1] + b1v;
            o1.x = acc[mt][nt][2] + b0v; o1.y = acc[mt][nt][3] + b1v;
            *(float2*)&C[(size_t)r0 * N + c0] = o0;
            *(float2*)&C[(size_t)(r0 + 8) * N + c0] = o1;
        }
}

// ---------------- persistent LSTM layer kernel: W in registers ----------------
// grid = 128: d = bi>>6, bg = (bi>>3)&7, ugi = bi&7. block = 256 threads.
// warp w: 4 units (u_in = w*4 + usub); lane = kq*4 + usub; thread owns W for
// (unit, 4 gates, k in [kq*32, kq*32+32)) = 128 regs, loaded once per layer.
// Partial gate sums reduced over kq via shfl butterfly; lane keeps batch b=kq.
__global__ __launch_bounds__(256) void lstm_layer_kernel(
    const float* __restrict__ wt_l,   // g_wt + l*524288
    const float* __restrict__ pre,    // g_pre
    float* __restrict__ out)
{
    __shared__ float hs[2048];        // h for this batch group: [u][b]
    const int bi  = blockIdx.x;
    const int d   = bi >> 6;
    const int bg  = (bi >> 3) & 7;
    const int ugi = bi & 7;
    const int tid = threadIdx.x;
    const int w    = tid >> 5;
    const int lane = tid & 31;
    const int usub = lane & 3;
    const int kq   = lane >> 2;
    const int u_in = w * 4 + usub;
    const int u    = ugi * 32 + u_in;      // unit id 0..255 within direction
    const int bglob = bg * 8 + kq;         // this lane's batch

    // load this thread's W slice into registers: 32 x float4 (kk-major, gates inner)
    ull wif[32], wgo[32];
    {
        const float4* wb = (const float4*)(wt_l
            + (((size_t)(d * 8 + ugi) * 32 + u_in) * 1024) + kq * 128);
#pragma unroll
        for (int j = 0; j < 32; j++) {
            float4 v = wb[j];
            wif[j] = pack2(v.x, v.y);
            wgo[j] = pack2(v.z, v.w);
        }
    }

    unsigned int* flags = &g_flag2[d * 64 + bg * 8];
    float c = 0.f;

    for (int s = 0; s < TT; s++) {
        const int tt = d ? (TT - 1 - s) : s;
        const int rp = s & 1, wp = rp ^ 1;

        // prefetch pre-activations for (tt, bglob, u): 4 gates
        const float* prow = pre + ((size_t)tt * BBATCH + bglob) * 2048 + d * G4;
        float p0 = __ldg(prow + u);
        float p1 = __ldg(prow + 256 + u);
        float p2 = __ldg(prow + 512 + u);
        float p3 = __ldg(prow + 768 + u);

        // wait for all 8 blocks of this group to finish step s-1
        if (s) {
            if (tid < 8) {
                const unsigned int* fp = flags + tid;
                unsigned int v;
                do {
                    asm volatile("ld.acquire.gpu.global.u32 %0, [%1];"
                                 : "=r"(v) : "l"(fp) : "memory");
                } while (v < (unsigned int)s);
            }
            __syncthreads();
        }

        // stage group h (parity rp) into smem via L2
        {
            const float4* hsrc = (const float4*)(g_hb + (((size_t)rp * 2 + d) * 8 + bg) * 2048);
#pragma unroll
            for (int i = tid; i < 512; i += 256) ((float4*)hs)[i] = __ldcg(hsrc + i);
        }
        __syncthreads();

        // partial gate sums over this thread's k-range, all 8 batches
        ull pif[8], pgo[8];
#pragma unroll
        for (int b2 = 0; b2 < 8; b2++) { pif[b2] = 0ull; pgo[b2] = 0ull; }
        const float* hp = hs + kq * 256;   // 32 k's x 8 batches
#pragma unroll
        for (int kk = 0; kk < 32; kk++) {
            float hv[8];
            *(float4*)hv       = *(const float4*)(hp + kk * 8);
            *(float4*)(hv + 4) = *(const float4*)(hp + kk * 8 + 4);
#pragma unroll
            for (int b2 = 0; b2 < 8; b2++) {
                ull hh = pack2(hv[b2], hv[b2]);
                ffma2(pif[b2], hh, wif[kk]);
                ffma2(pgo[b2], hh, wgo[kk]);
            }
        }

        // butterfly-reduce over kq (lane bits 2..4)
#pragma unroll
        for (int rnd = 4; rnd <= 16; rnd <<= 1) {
#pragma unroll
            for (int b2 = 0; b2 < 8; b2++) {
                pif[b2] = addx2(pif[b2], __shfl_xor_sync(0xffffffffu, pif[b2], rnd));
                pgo[b2] = addx2(pgo[b2], __shfl_xor_sync(0xffffffffu, pgo[b2], rnd));
            }
        }

        // select this lane's batch (b = kq)
        ull q0 = (kq & 1) ? pif[1] : pif[0];
        ull q1 = (kq & 1) ? pif[3] : pif[2];
        ull q2 = (kq & 1) ? pif[5] : pif[4];
        ull q3 = (kq & 1) ? pif[7] : pif[6];
        ull r0 = (kq & 2) ? q1 : q0;
        ull r1 = (kq & 2) ? q3 : q2;
        ull sif = (kq & 4) ? r1 : r0;
        q0 = (kq & 1) ? pgo[1] : pgo[0];
        q1 = (kq & 1) ? pgo[3] : pgo[2];
        q2 = (kq & 1) ? pgo[5] : pgo[4];
        q3 = (kq & 1) ? pgo[7] : pgo[6];
        r0 = (kq & 2) ? q1 : q0;
        r1 = (kq & 2) ? q3 : q2;
        ull sgo = (kq & 4) ? r1 : r0;

        float gi, gf, gg, go;
        unpack2(gi, gf, sif);
        unpack2(gg, go, sgo);
        gi += p0; gf += p1; gg += p2; go += p3;

        float iv = 1.f / (1.f + expf(-gi));
        float fv = 1.f / (1.f + expf(-gf));
        float gv = tanhf(gg);
        float ov = 1.f / (1.f + expf(-go));
        c = fv * c + iv * gv;
        float h = ov * tanhf(c);

        // store h for next step (parity wp) and to layer output
        g_hb[(((size_t)wp * 2 + d) * 8 + bg) * 2048 + u_in * 8 + kq
             + (size_t)ugi * 256] = h;
        out[((size_t)tt * BBATCH + bglob) * HD2 + d * HH + u] = h;

        // release: signal this block finished step s
        __syncthreads();
        if (tid == 0) {
            asm volatile("st.release.gpu.global.u32 [%0], %1;"
                         :: "l"(flags + ugi), "r"((unsigned int)(s + 1)) : "memory");
        }
    }
}

// ---------------- attention ----------------
__global__ __launch_bounds__(256) void energy_kernel(const float* __restrict__ z,
                                                     const float* __restrict__ aw2,
                                                     const float* __restrict__ ab2)
{
    int w = threadIdx.x >> 5, lane = threadIdx.x & 31;
    int r = blockIdx.x * 8 + w;
    const float* zr = z + (size_t)r * 512;
    float acc = 0.f;
#pragma unroll
    for (int j = 0; j < 16; j++) {
        int k = lane + j * 32;
        acc += tanhf(zr[k]) * aw2[k];
    }
#pragma unroll
    for (int o = 16; o > 0; o >>= 1) acc += __shfl_down_sync(0xffffffffu, acc, o);
    if (lane == 0) g_energy[r] = acc + ab2[0];
}

__global__ __launch_bounds__(256) void softmax_kernel() {
    __shared__ float red[256];
    int b = blockIdx.x, t = threadIdx.x;
    float e = g_energy[t * 64 + b];
    red[t] = e;
    __syncthreads();
    for (int s = 128; s > 0; s >>= 1) {
        if (t < s) red[t] = fmaxf(red[t], red[t + s]);
        __syncthreads();
    }
    float m = red[0];
    __syncthreads();
    float p = expf(e - m);
    red[t] = p;
    __syncthreads();
    for (int s = 128; s > 0; s >>= 1) {
        if (t < s) red[t] += red[t + s];
        __syncthreads();
    }
    g_energy[t * 64 + b] = p / red[0];
}

__global__ __launch_bounds__(256) void feats_kernel(const float* __restrict__ y,
                                                    const float* __restrict__ hw,
                                                    const float* __restrict__ hb)
{
    int w = threadIdx.x >> 5, lane = threadIdx.x & 31;
    int r = blockIdx.x * 8 + w;
    const float* yr = y + (size_t)r * 512;
    float acc[NTAGS];
#pragma unroll
    for (int i = 0; i < NTAGS; i++) acc[i] = 0.f;
#pragma unroll
    for (int j = 0; j < 16; j++) {
        int k = lane + j * 32;
        float v = yr[k];
#pragma unroll
        for (int i = 0; i < NTAGS; i++) acc[i] += v * hw[i * 512 + k];
    }
#pragma unroll
    for (int i = 0; i < NTAGS; i++)
#pragma unroll
        for (int o = 16; o > 0; o >>= 1) acc[i] += __shfl_down_sync(0xffffffffu, acc[i], o);
    if (lane == 0) {
        float wt = 1.f + g_energy[r];
        int b = r & 63, t = r >> 6;
#pragma unroll
        for (int i = 0; i < NTAGS; i++)
            g_feats[((size_t)b * TT + t) * NTAGS + i] = wt * acc[i] + hb[i];
    }
}

// ---------------- CRF ----------------
__global__ __launch_bounds__(32) void crf_kernel(const int* __restrict__ tags,
                                                 const float* __restrict__ mask,
                                                 const float* __restrict__ trans,
                                                 float* __restrict__ out)
{
    __shared__ float tr[36];
    int b = blockIdx.x, lid = threadIdx.x;
    for (int i = lid; i < 36; i += 32) tr[i] = trans[i];
    __syncwarp();

    const int ii = lid % NTAGS;
    const float* fb = g_feats + (size_t)b * TT * NTAGS;
    const float* mb = mask + (size_t)b * TT;

    float fv = (ii == TAG_START) ? 0.f : NEGV;
    for (int t = 0; t < TT; t++) {
        float fj[NTAGS];
#pragma unroll
        for (int j = 0; j < NTAGS; j++) fj[j] = __shfl_sync(0xffffffffu, fv, j);
        float v[NTAGS];
        float m = -3.4e38f;
#pragma unroll
        for (int j = 0; j < NTAGS; j++) {
            v[j] = fj[j] + tr[ii * NTAGS + j];
            m = fmaxf(m, v[j]);
        }
        float ssum = 0.f;
#pragma unroll
        for (int j = 0; j < NTAGS; j++) ssum += expf(v[j] - m);
        float nxt = m + logf(ssum) + fb[t * NTAGS + ii];
        fv = (mb[t] > 0.f) ? nxt : fv;
    }
    float sv = fv + tr[TAG_STOP * NTAGS + ii];
    float gvals[NTAGS];
#pragma unroll
    for (int j = 0; j < NTAGS; j++) gvals[j] = __shfl_sync(0xffffffffu, sv, j);
    float m2 = -3.4e38f;
#pragma unroll
    for (int j = 0; j < NTAGS; j++) m2 = fmaxf(m2, gvals[j]);
    float s2 = 0.f;
#pragma unroll
    for (int j = 0; j < NTAGS; j++) s2 += expf(gvals[j] - m2);
    float fwd = m2 + logf(s2);

    float gold = 0.f, msum = 0.f;
    for (int t = lid; t < TT; t += 32) {
        int cur = tags[b * TT + t];
        int prev = t ? tags[b * TT + t - 1] : TAG_START;
        float mm = mb[t];
        gold += (fb[t * NTAGS + cur] + tr[cur * NTAGS + prev]) * mm;
        msum += mm;
    }
#pragma unroll
    for (int o = 16; o > 0; o >>= 1) {
        gold += __shfl_down_sync(0xffffffffu, gold, o);
        msum += __shfl_down_sync(0xffffffffu, msum, o);
    }
    if (lid == 0) {
        int sl = (int)(msum + 0.5f);
        int last = (sl > 0) ? tags[b * TT + sl - 1] : TAG_START;
        gold += tr[TAG_STOP * NTAGS + last];
        atomicAdd(out, (fwd - gold) * (1.f / 64.f));
    }
}

// ---------------- launch ----------------
extern "C" void kernel_launch(void* const* d_in, const int* in_sizes, int n_in,
                              void* d_out, int out_size)
{
    const int*   sentences = (const int*)d_in[0];
    const int*   tags      = (const int*)d_in[1];
    const float* mask      = (const float*)d_in[2];
    const float* embed     = (const float*)d_in[3];
    const float* w_ih      = (const float*)d_in[4];
    const float* w_hh      = (const float*)d_in[5];
    const float* b_ih      = (const float*)d_in[6];
    const float* b_hh      = (const float*)d_in[7];
    const float* aw1       = (const float*)d_in[8];
    const float* ab1       = (const float*)d_in[9];
    const float* aw2       = (const float*)d_in[10];
    const float* ab2       = (const float*)d_in[11];
    const float* hw        = (const float*)d_in[12];
    const float* hb        = (const float*)d_in[13];
    const float* trans     = (const float*)d_in[14];
    float* out = (float*)d_out;

    zero_out_kernel<<<1, 1>>>(out);
    bias_kernel<<<24, 256>>>(b_ih, b_hh);
    wt_kernel<<<6144, 256>>>(w_hh);
    embed_kernel<<<32768, 256>>>(sentences, embed);

    float *px, *py, *ppre, *pbias, *pwt;
    __nv_bfloat16 *pah, *pal, *pwh2, *pwl2;
    cudaGetSymbolAddress((void**)&px, g_x);
    cudaGetSymbolAddress((void**)&py, g_y);
    cudaGetSymbolAddress((void**)&ppre, g_pre);
    cudaGetSymbolAddress((void**)&pbias, g_bias);
    cudaGetSymbolAddress((void**)&pwt, g_wt);
    cudaGetSymbolAddress((void**)&pah, g_ah);
    cudaGetSymbolAddress((void**)&pal, g_al);
    cudaGetSymbolAddress((void**)&pwh2, g_wh2);
    cudaGetSymbolAddress((void**)&pwl2, g_wl2);

    const int M = TT * BBATCH;        // 16384
    const int NA = M * EE;            // 8388608
    const int NWIH = 3 * 2 * G4 * EE; // 3145728

    cvt_split_kernel<<<NWIH / 4 / 256, 256>>>(w_ih, pwh2, pwl2, NWIH / 4);
    cvt_split_kernel<<<512 * 512 / 4 / 256, 256>>>(aw1, pwh2 + NWIH, pwl2 + NWIH, 512 * 512 / 4);

    float* lin = px;
    float* lout = py;
    for (int l = 0; l < 3; l++) {
        zero_state_kernel<<<256, 256>>>();
        cvt_split_kernel<<<NA / 4 / 256, 256>>>(lin, pah, pal, NA / 4);
        dim3 g1(2048 / 128, M / 128);
        gemm_tc_kernel<<<g1, 256>>>(pah, pal,
                                    pwh2 + (size_t)l * 2 * G4 * EE,
                                    pwl2 + (size_t)l * 2 * G4 * EE,
                                    pbias + l * 2048, ppre, M, 2048, EE);
        const float* wtl = pwt + (size_t)l * 2 * 8 * 32768;
        lstm_layer_kernel<<<128, 256>>>(wtl, ppre, lout);
        float* tmp = lin; lin = lout; lout = tmp;
    }
    float* lstm_out = lin;   // == py
    float* zbuf = lout;      // == px

    cvt_split_kernel<<<NA / 4 / 256, 256>>>(lstm_out, pah, pal, NA / 4);
    dim3 g2(512 / 128, M / 128);
    gemm_tc_kernel<<<g2, 256>>>(pah, pal, pwh2 + NWIH, pwl2 + NWIH,
                                ab1, zbuf, M, 512, EE);
    energy_kernel<<<M / 8, 256>>>(zbuf, aw2, ab2);
    softmax_kernel<<<BBATCH, 256>>>();
    feats_kernel<<<M / 8, 256>>>(lstm_out, hw, hb);
    crf_kernel<<<BBATCH, 32>>>(tags, mask, trans, out);
}